// round 11
// baseline (speedup 1.0000x reference)
#include <cuda_runtime.h>
#include <cstdint>
#include <math.h>

// ---------------------------------------------------------------------------
// NeuralODE Tsit5 — persistent-CTA fp32 kernel, round 9.
// RC=128 register tile (16 rows x 8 cols/thread) to break the crossbar/issue
// co-limit (wf/ffma2 = 0.1875):
//   per warp-k: 4 uniform LDS.128 (A, 1 wf each) + 2 swizzled LDS.128 (W, 8 wf)
//               + 8 pk2 + 64 ffma2
// 256 threads, 8 warps = 2 row-groups x 4 k-slices; R7's cp.async W tiles
// and 3-phase split-K reduction retained.
// ---------------------------------------------------------------------------

#define BATCH   4096
#define DIM     64
#define WIDTH   256
#define NTT     101
#define TM      32
#define NCTA    (BATCH / TM)      // 128
#define THREADS 256

// row swizzle: element r of feature-row n lives at slot r ^ SWR(n) (mult of 4)
#define SWR(idx) ((((idx) >> 3) & 7) << 2)
// chunk swizzle for W tiles (16B chunks within a row)
__device__ __forceinline__ int swc(int j) { return j ^ ((j >> 3) & 7); }

#define ACT_SIZE (WIDTH * TM)     // 8192 floats
#define ZK_SIZE  (DIM * TM)       // 2048 floats
#define WTILE_F  (32 * WIDTH)     // 8192 floats per 32-row tile

#define SMEM_FLOATS (ACT_SIZE + ACT_SIZE + 2*WTILE_F + ZK_SIZE + ZK_SIZE + 6*ZK_SIZE)
#define SMEM_BYTES  (SMEM_FLOATS * 4)   // 192KB

// Tsit5 tableau
__constant__ float c_A[6][5] = {
    {0.f, 0.f, 0.f, 0.f, 0.f},
    {0.161f, 0.f, 0.f, 0.f, 0.f},
    {-0.008480655492356989f, 0.335480655492357f, 0.f, 0.f, 0.f},
    {2.8971530571054935f, -6.359448489975075f, 4.3622954328695815f, 0.f, 0.f},
    {5.325864828439257f, -11.748883564062828f, 7.4955393428898365f, -0.09249506636175525f, 0.f},
    {5.86145544294642f, -12.92096931784711f, 8.159367898576159f, -0.071584973281401f, -0.028269050394068383f}
};
__constant__ float c_B[6] = {
    0.09646076681806523f, 0.01f, 0.4798896504144996f,
    1.379008574103742f, -3.290069515436081f, 2.324710524099774f
};

// ---- packed f32x2 helpers ----
__device__ __forceinline__ unsigned long long pk2(float lo, float hi) {
    unsigned long long r;
    asm("mov.b64 %0, {%1, %2};" : "=l"(r) : "f"(lo), "f"(hi));
    return r;
}
__device__ __forceinline__ void upk2(unsigned long long v, float &lo, float &hi) {
    asm("mov.b64 {%0, %1}, %2;" : "=f"(lo), "=f"(hi) : "l"(v));
}
__device__ __forceinline__ void ffma2(unsigned long long &d,
                                      unsigned long long a,
                                      unsigned long long b) {
    asm("fma.rn.f32x2 %0, %1, %2, %0;" : "+l"(d) : "l"(a), "l"(b));
}

// ---- cp.async helpers ----
__device__ __forceinline__ void cpa16(float *smem_dst, const float *gmem_src) {
    unsigned s = (unsigned)__cvta_generic_to_shared(smem_dst);
    asm volatile("cp.async.cg.shared.global [%0], [%1], 16;" :: "r"(s), "l"(gmem_src));
}
__device__ __forceinline__ void cpa_commit() {
    asm volatile("cp.async.commit_group;");
}
__device__ __forceinline__ void cpa_wait_all() {
    asm volatile("cp.async.wait_group 0;");
}

// ---------------------------------------------------------------------------
// Copy W tile t into SMEM (chunk-swizzled). Tile = 4 sub-tiles (one per
// k-slice) of 8 rows x N cols. Source row for (slice s, local kk):
//   s*(K/4) + t*8 + kk.
// ---------------------------------------------------------------------------
template <int K, int N>
__device__ __forceinline__ void copy_tile(float *dst, const float *__restrict__ Wg, int t) {
    constexpr int CPR    = N / 4;        // 16B chunks per row
    constexpr int CHUNKS = 32 * CPR;
#pragma unroll
    for (int m = threadIdx.x; m < CHUNKS; m += THREADS) {
        const int row = m / CPR;
        const int j   = m % CPR;
        const int s   = row >> 3;
        const int kk  = row & 7;
        const float *src = Wg + (size_t)(s * (K / 4) + t * 8 + kk) * N + j * 4;
        cpa16(dst + (size_t)row * N + swc(j) * 4, src);
    }
}

// ---------------------------------------------------------------------------
// Dense layer, split-K=4, thread tile 16 rows x CPL cols:
//   Aout[c][r^SWR(c)] = act( sum_k W[k][c] * Ain[k][r^SWR(k)] + b[c] )
// Warp w: ks = w>>1 (k-slice 0..3), rg = w&1 (rows rg*16..+15).
// Lane: CPL = N/32 columns at lane*CPL.
// red1 MAY alias Ain/Aout (act): phase ordering + syncs make it safe (as R7).
// ---------------------------------------------------------------------------
template <int K, int N, bool ACT>
__device__ __forceinline__ void layerT(const float *Ain, float *Aout,
                                       const float *__restrict__ Wg,
                                       const float *__restrict__ bg,
                                       float *wbuf, float *red0, float *red1) {
    constexpr int CPL   = N / 32;        // 8 or 2
    constexpr int TILES = K / 32;
    constexpr int KSLEN = K / 4;

    const int tid  = threadIdx.x;
    const int w    = tid >> 5;
    const int lane = tid & 31;
    const int ks   = w >> 1;
    const int rg   = w & 1;
    const int r0   = rg * 16;
    const int c0   = lane * CPL;

    // hoisted swizzled W offsets (floats)
    int wo0, wo1;
    if constexpr (CPL == 8) {
        wo0 = swc(2 * lane) * 4;
        wo1 = swc(2 * lane + 1) * 4;
    } else {
        wo0 = swc(lane >> 1) * 4 + (lane & 1) * 2;
        wo1 = 0;
    }

    // acc[p][c]: row-pair p (rows r0+2p, r0+2p+1), col c0+c
    unsigned long long acc[8][CPL];
    if (ks == 0) {
#pragma unroll
        for (int c = 0; c < CPL; c++) {
            float b = __ldg(bg + c0 + c);
            unsigned long long bb = pk2(b, b);
#pragma unroll
            for (int p = 0; p < 8; p++) acc[p][c] = bb;
        }
    } else {
#pragma unroll
        for (int p = 0; p < 8; p++)
#pragma unroll
            for (int c = 0; c < CPL; c++) acc[p][c] = 0ull;
    }

    copy_tile<K, N>(wbuf, Wg, 0);
    cpa_commit();

    for (int t = 0; t < TILES; ++t) {
        cpa_wait_all();
        __syncthreads();
        if (t + 1 < TILES) {
            copy_tile<K, N>(wbuf + ((t + 1) & 1) * WTILE_F, Wg, t + 1);
            cpa_commit();
        }

        const float *wt = wbuf + (t & 1) * WTILE_F + (size_t)(ks * 8) * N;
        const int kbase = ks * KSLEN + t * 8;
        const int swk   = SWR(kbase);          // constant across this tile's 8 k
        const float *a0 = Ain + kbase * TM + ((r0 +  0) ^ swk);
        const float *a1 = Ain + kbase * TM + ((r0 +  4) ^ swk);
        const float *a2 = Ain + kbase * TM + ((r0 +  8) ^ swk);
        const float *a3 = Ain + kbase * TM + ((r0 + 12) ^ swk);

#pragma unroll
        for (int kk = 0; kk < 8; ++kk) {
            // A: 16 rows of column k as 4 uniform LDS.128 (packed f32x2 pairs)
            ulonglong2 A0 = *reinterpret_cast<const ulonglong2 *>(a0 + kk * TM);
            ulonglong2 A1 = *reinterpret_cast<const ulonglong2 *>(a1 + kk * TM);
            ulonglong2 A2 = *reinterpret_cast<const ulonglong2 *>(a2 + kk * TM);
            ulonglong2 A3 = *reinterpret_cast<const ulonglong2 *>(a3 + kk * TM);

            const float *wr = wt + kk * N;
            float wv[CPL];
            if constexpr (CPL == 8) {
                float4 x = *reinterpret_cast<const float4 *>(wr + wo0);
                float4 y = *reinterpret_cast<const float4 *>(wr + wo1);
                wv[0]=x.x; wv[1]=x.y; wv[2]=x.z; wv[3]=x.w;
                wv[4]=y.x; wv[5]=y.y; wv[6]=y.z; wv[7]=y.w;
            } else {
                float2 x = *reinterpret_cast<const float2 *>(wr + wo0);
                wv[0]=x.x; wv[1]=x.y;
            }

#pragma unroll
            for (int c = 0; c < CPL; c++) {
                unsigned long long wp = pk2(wv[c], wv[c]);
                ffma2(acc[0][c], A0.x, wp);
                ffma2(acc[1][c], A0.y, wp);
                ffma2(acc[2][c], A1.x, wp);
                ffma2(acc[3][c], A1.y, wp);
                ffma2(acc[4][c], A2.x, wp);
                ffma2(acc[5][c], A2.y, wp);
                ffma2(acc[6][c], A3.x, wp);
                ffma2(acc[7][c], A3.y, wp);
            }
        }
    }

    // SYNC-A: all k-loop reads complete before red1(=act) writes
    __syncthreads();

    // phase 1: ks2 -> red0, ks3 -> red1
    if (ks >= 2) {
        float *dst = (ks == 2) ? red0 : red1;
#pragma unroll
        for (int c = 0; c < CPL; c++) {
            const int cc = c0 + c;
            const int sc = SWR(cc);
            float *base = dst + cc * TM;
#pragma unroll
            for (int q = 0; q < 4; q++) {
                float a0v, a1v, a2v, a3v;
                upk2(acc[2*q][c],   a0v, a1v);
                upk2(acc[2*q+1][c], a2v, a3v);
                float4 v; v.x=a0v; v.y=a1v; v.z=a2v; v.w=a3v;
                *reinterpret_cast<float4 *>(base + ((r0 + 4*q) ^ sc)) = v;
            }
        }
    }
    __syncthreads();

    // phase 2: ks1: acc + red0 + red1 -> red0
    if (ks == 1) {
#pragma unroll
        for (int c = 0; c < CPL; c++) {
            const int cc = c0 + c;
            const int sc = SWR(cc);
            float *b0p = red0 + cc * TM;
            const float *b1p = red1 + cc * TM;
#pragma unroll
            for (int q = 0; q < 4; q++) {
                const int off = (r0 + 4*q) ^ sc;
                float4 v0 = *reinterpret_cast<const float4 *>(b0p + off);
                float4 v1 = *reinterpret_cast<const float4 *>(b1p + off);
                float a0v, a1v, a2v, a3v;
                upk2(acc[2*q][c],   a0v, a1v);
                upk2(acc[2*q+1][c], a2v, a3v);
                float4 v;
                v.x = a0v + v0.x + v1.x;
                v.y = a1v + v0.y + v1.y;
                v.z = a2v + v0.z + v1.z;
                v.w = a3v + v0.w + v1.w;
                *reinterpret_cast<float4 *>(b0p + off) = v;
            }
        }
    }
    __syncthreads();

    // phase 3: ks0: acc + red0 (bias already in acc), tanh -> Aout
    if (ks == 0) {
#pragma unroll
        for (int c = 0; c < CPL; c++) {
            const int cc = c0 + c;
            const int sc = SWR(cc);
            const float *b0p = red0 + cc * TM;
            float *dst = Aout + cc * TM;
#pragma unroll
            for (int q = 0; q < 4; q++) {
                const int off = (r0 + 4*q) ^ sc;
                float4 v0 = *reinterpret_cast<const float4 *>(b0p + off);
                float a0v, a1v, a2v, a3v;
                upk2(acc[2*q][c],   a0v, a1v);
                upk2(acc[2*q+1][c], a2v, a3v);
                float4 v;
                v.x = a0v + v0.x;
                v.y = a1v + v0.y;
                v.z = a2v + v0.z;
                v.w = a3v + v0.w;
                if (ACT) {
                    v.x = tanhf(v.x); v.y = tanhf(v.y);
                    v.z = tanhf(v.z); v.w = tanhf(v.w);
                }
                *reinterpret_cast<float4 *>(dst + off) = v;
            }
        }
    }
    __syncthreads();
}

// ---------------------------------------------------------------------------
__global__ void __launch_bounds__(THREADS, 1)
node_kernel(const float *__restrict__ ts, const float *__restrict__ y0,
            const float *__restrict__ W0, const float *__restrict__ b0,
            const float *__restrict__ W1, const float *__restrict__ b1,
            const float *__restrict__ W2, const float *__restrict__ b2,
            const float *__restrict__ W3, const float *__restrict__ b3,
            float *__restrict__ out) {
    extern __shared__ float sm[];
    float *act  = sm;                    // 8192, [256][32] row-swizzled
    float *red0 = act + ACT_SIZE;        // 8192
    float *wbuf = red0 + ACT_SIZE;       // 16384 (2 tiles)
    float *zbuf = wbuf + 2 * WTILE_F;    // 2048, [64][32] row-swizzled
    float *ybuf = zbuf + ZK_SIZE;        // 2048
    float *kbuf = ybuf + ZK_SIZE;        // 6 * 2048
    float *red1 = act;                   // aliases act (safe, see layerT)

    const int tid = threadIdx.x;
    const int cta = blockIdx.x;

    // ingest y0 (row-major) -> ybuf (transposed, row-swizzled); emit out[0]
    {
        const float *y0c = y0 + (size_t)cta * TM * DIM;
        float *o0 = out + (size_t)cta * TM * DIM;
        for (int i = tid; i < TM * DIM; i += THREADS) {
            const int r = i >> 6;
            const int d = i & 63;
            float v = __ldg(y0c + i);
            ybuf[d * TM + (r ^ SWR(d))] = v;
            o0[i] = v;
        }
    }
    __syncthreads();

    for (int t = 1; t < NTT; ++t) {
        const float h = __ldg(ts + t) - __ldg(ts + t - 1);

        for (int s = 0; s < 6; ++s) {
            const float *zin;
            if (s == 0) {
                zin = ybuf;
            } else {
                // z = y + h * sum_{j<s} A[s][j]*k_j (elementwise, same layout)
                float4 *zb = reinterpret_cast<float4 *>(zbuf);
                const float4 *yb = reinterpret_cast<const float4 *>(ybuf);
                for (int i = tid; i < ZK_SIZE / 4; i += THREADS) {
                    float4 v = yb[i];
                    for (int j = 0; j < s; j++) {
                        float c = h * c_A[s][j];
                        float4 kv = reinterpret_cast<const float4 *>(kbuf + j * ZK_SIZE)[i];
                        v.x += c * kv.x; v.y += c * kv.y;
                        v.z += c * kv.z; v.w += c * kv.w;
                    }
                    zb[i] = v;
                }
                __syncthreads();
                zin = zbuf;
            }

            layerT<DIM,   WIDTH, true >(zin, act, W0, b0, wbuf, red0, red1);
            layerT<WIDTH, WIDTH, true >(act, act, W1, b1, wbuf, red0, red1);
            layerT<WIDTH, WIDTH, true >(act, act, W2, b2, wbuf, red0, red1);
            layerT<WIDTH, DIM,   false>(act, kbuf + s * ZK_SIZE, W3, b3, wbuf, red0, red1);
        }

        // y += h * sum_j B[j]*k_j (elementwise)
        {
            float4 *yb = reinterpret_cast<float4 *>(ybuf);
            for (int i = tid; i < ZK_SIZE / 4; i += THREADS) {
                float4 v = yb[i];
#pragma unroll
                for (int j = 0; j < 6; j++) {
                    float c = h * c_B[j];
                    float4 kv = reinterpret_cast<const float4 *>(kbuf + j * ZK_SIZE)[i];
                    v.x += c * kv.x; v.y += c * kv.y;
                    v.z += c * kv.z; v.w += c * kv.w;
                }
                yb[i] = v;
            }
        }
        __syncthreads();

        // store out[t] (row-major, coalesced) from swizzled ybuf
        {
            float *outc = out + (size_t)t * (BATCH * DIM) + (size_t)cta * TM * DIM;
            for (int i = tid; i < TM * DIM; i += THREADS) {
                const int r = i >> 6;
                const int d = i & 63;
                outc[i] = ybuf[d * TM + (r ^ SWR(d))];
            }
        }
        __syncthreads();
    }
}

// ---------------------------------------------------------------------------
extern "C" void kernel_launch(void *const *d_in, const int *in_sizes, int n_in,
                              void *d_out, int out_size) {
    const float *ts = (const float *)d_in[0];
    const float *y0 = (const float *)d_in[1];
    const float *W0 = (const float *)d_in[2];
    const float *b0 = (const float *)d_in[3];
    const float *W1 = (const float *)d_in[4];
    const float *b1 = (const float *)d_in[5];
    const float *W2 = (const float *)d_in[6];
    const float *b2 = (const float *)d_in[7];
    const float *W3 = (const float *)d_in[8];
    const float *b3 = (const float *)d_in[9];
    float *out = (float *)d_out;

    cudaFuncSetAttribute(node_kernel,
                         cudaFuncAttributeMaxDynamicSharedMemorySize, SMEM_BYTES);
    node_kernel<<<NCTA, THREADS, SMEM_BYTES>>>(ts, y0, W0, b0, W1, b1,
                                               W2, b2, W3, b3, out);
}

// round 12
// speedup vs baseline: 1.5013x; 1.5013x over previous
#include <cuda_runtime.h>
#include <cstdint>
#include <math.h>

// ---------------------------------------------------------------------------
// NeuralODE Tsit5 — persistent-CTA fp32 kernel, round 11.
// = the proven 22.8ms kernel (512thr/TM=32) rescaled to TM=16, 256 threads,
//   NCTA=256, __launch_bounds__(256,2): TWO independent CTAs per SM so that
//   barrier/latency stalls of one CTA are covered by the other's warps.
// Per-SM FMA and L1 demand identical to the 22.8ms config.
// ---------------------------------------------------------------------------

#define BATCH   4096
#define DIM     64
#define WIDTH   256
#define NTT     101
#define TM      16
#define NCTA    (BATCH / TM)      // 256
#define THREADS 256

// row swizzle: element r (0..15) of feature-row n at slot r ^ SWR(n)
#define SWR(idx) ((((idx) >> 3) & 3) << 2)   // {0,4,8,12}, constant per 8-k group

#define ACT_SIZE (WIDTH * TM)     // 4096 floats (16KB)
#define ZK_SIZE  (DIM * TM)       // 1024 floats (4KB)
#define RED_SIZE (WIDTH * TM)     // 4096 floats

#define SMEM_FLOATS (2*ACT_SIZE + 2*RED_SIZE + ZK_SIZE + ZK_SIZE + 6*ZK_SIZE)
#define SMEM_BYTES  (SMEM_FLOATS * 4)   // 96KB per CTA -> 2 CTAs/SM

// Tsit5 tableau
__constant__ float c_A[6][5] = {
    {0.f, 0.f, 0.f, 0.f, 0.f},
    {0.161f, 0.f, 0.f, 0.f, 0.f},
    {-0.008480655492356989f, 0.335480655492357f, 0.f, 0.f, 0.f},
    {2.8971530571054935f, -6.359448489975075f, 4.3622954328695815f, 0.f, 0.f},
    {5.325864828439257f, -11.748883564062828f, 7.4955393428898365f, -0.09249506636175525f, 0.f},
    {5.86145544294642f, -12.92096931784711f, 8.159367898576159f, -0.071584973281401f, -0.028269050394068383f}
};
__constant__ float c_B[6] = {
    0.09646076681806523f, 0.01f, 0.4798896504144996f,
    1.379008574103742f, -3.290069515436081f, 2.324710524099774f
};

// ---- packed f32x2 helpers ----
__device__ __forceinline__ unsigned long long pk2(float lo, float hi) {
    unsigned long long r;
    asm("mov.b64 %0, {%1, %2};" : "=l"(r) : "f"(lo), "f"(hi));
    return r;
}
__device__ __forceinline__ void upk2(unsigned long long v, float &lo, float &hi) {
    asm("mov.b64 {%0, %1}, %2;" : "=f"(lo), "=f"(hi) : "l"(v));
}
__device__ __forceinline__ void ffma2(unsigned long long &d,
                                      unsigned long long a,
                                      unsigned long long b) {
    asm("fma.rn.f32x2 %0, %1, %2, %0;" : "+l"(d) : "l"(a), "l"(b));
}

// ---------------------------------------------------------------------------
// Dense layer, split-K=4, thread tile 8 rows x CPL cols (R5 geometry):
//   Aout[c][r^SWR(c)] = act( sum_k W[k][c] * Ain[k][r^SWR(k)] + b[c] )
// Warp w (8 warps): ks = w>>1 (k-slice 0..3), rg = w&1 (rows rg*8..+7).
// Lane: CPL = N/32 columns at lane*CPL. W via LDG (L2-resident), 1-deep
// prefetch. 3-phase SMEM split-K reduction.
// ---------------------------------------------------------------------------
template <int K, int N, bool ACT>
__device__ __forceinline__ void layerT(const float *Ain, float *Aout,
                                       const float *__restrict__ Wg,
                                       const float *__restrict__ bg,
                                       float *red0, float *red1) {
    constexpr int CPL  = N / 32;       // 8 (N=256) or 2 (N=64)
    constexpr int KS   = K / 4;        // 64 or 16
    constexpr int NGRP = KS / 8;       // 8 or 2

    const int tid  = threadIdx.x;
    const int w    = tid >> 5;
    const int lane = tid & 31;
    const int rg   = w & 1;
    const int ks   = w >> 1;
    const int r0   = rg * 8;
    const int c0   = lane * CPL;

    unsigned long long acc[4][CPL];
    if (ks == 0) {
#pragma unroll
        for (int c = 0; c < CPL; c++) {
            float b = __ldg(bg + c0 + c);
            unsigned long long bb = pk2(b, b);
#pragma unroll
            for (int p = 0; p < 4; p++) acc[p][c] = bb;
        }
    } else {
#pragma unroll
        for (int p = 0; p < 4; p++)
#pragma unroll
            for (int c = 0; c < CPL; c++) acc[p][c] = 0ull;
    }

    // ---- W prefetch pipeline (1-deep), W via LDG ----
    const float *Wk = Wg + (size_t)(ks * KS) * N + c0;
    float wn[CPL];
    if constexpr (CPL == 8) {
        float4 wa = __ldg(reinterpret_cast<const float4 *>(Wk));
        float4 wb = __ldg(reinterpret_cast<const float4 *>(Wk + 4));
        wn[0]=wa.x; wn[1]=wa.y; wn[2]=wa.z; wn[3]=wa.w;
        wn[4]=wb.x; wn[5]=wb.y; wn[6]=wb.z; wn[7]=wb.w;
    } else {
        float2 wa = __ldg(reinterpret_cast<const float2 *>(Wk));
        wn[0]=wa.x; wn[1]=wa.y;
    }
    Wk += N;

    for (int g = 0; g < NGRP; ++g) {
        const int kbase = ks * KS + g * 8;
        const int swk   = SWR(kbase);       // constant over the 8-group
        const float *p0 = Ain + kbase * TM + ((r0 + 0) ^ swk);
        const float *p1 = Ain + kbase * TM + ((r0 + 2) ^ swk);
        const float *p2 = Ain + kbase * TM + ((r0 + 4) ^ swk);
        const float *p3 = Ain + kbase * TM + ((r0 + 6) ^ swk);

#pragma unroll
        for (int kk = 0; kk < 8; ++kk) {
            // A row-pair broadcasts (uniform LDS.64, immediate offsets)
            unsigned long long ap0 = *reinterpret_cast<const unsigned long long *>(p0 + kk * TM);
            unsigned long long ap1 = *reinterpret_cast<const unsigned long long *>(p1 + kk * TM);
            unsigned long long ap2 = *reinterpret_cast<const unsigned long long *>(p2 + kk * TM);
            unsigned long long ap3 = *reinterpret_cast<const unsigned long long *>(p3 + kk * TM);

            // consume prefetched W, prefetch next
            float wc[CPL];
#pragma unroll
            for (int c = 0; c < CPL; c++) wc[c] = wn[c];

            if (kk < 7 || g + 1 < NGRP) {
                if constexpr (CPL == 8) {
                    float4 wa = __ldg(reinterpret_cast<const float4 *>(Wk));
                    float4 wb = __ldg(reinterpret_cast<const float4 *>(Wk + 4));
                    wn[0]=wa.x; wn[1]=wa.y; wn[2]=wa.z; wn[3]=wa.w;
                    wn[4]=wb.x; wn[5]=wb.y; wn[6]=wb.z; wn[7]=wb.w;
                } else {
                    float2 wa = __ldg(reinterpret_cast<const float2 *>(Wk));
                    wn[0]=wa.x; wn[1]=wa.y;
                }
            }
            Wk += N;

#pragma unroll
            for (int c = 0; c < CPL; c++) {
                unsigned long long wp = pk2(wc[c], wc[c]);
                ffma2(acc[0][c], ap0, wp);
                ffma2(acc[1][c], ap1, wp);
                ffma2(acc[2][c], ap2, wp);
                ffma2(acc[3][c], ap3, wp);
            }
        }
    }

    // ---- partial stores: ks2 -> red0, ks3 -> red1 ----
    if (ks >= 2) {
        float *dst = (ks == 2) ? red0 : red1;
#pragma unroll
        for (int c = 0; c < CPL; c++) {
            const int cc  = c0 + c;
            const int swcv = SWR(cc);
            float *base = dst + cc * TM;
#pragma unroll
            for (int q = 0; q < 2; q++) {
                float a0, a1, a2, a3;
                upk2(acc[2*q][c],   a0, a1);
                upk2(acc[2*q+1][c], a2, a3);
                float4 v; v.x=a0; v.y=a1; v.z=a2; v.w=a3;
                *reinterpret_cast<float4 *>(base + ((r0 + 4*q) ^ swcv)) = v;
            }
        }
    }
    __syncthreads();

    // ---- ks1: acc + red0 + red1 -> red0 ----
    if (ks == 1) {
#pragma unroll
        for (int c = 0; c < CPL; c++) {
            const int cc  = c0 + c;
            const int swcv = SWR(cc);
            float *b0p = red0 + cc * TM;
            const float *b1p = red1 + cc * TM;
#pragma unroll
            for (int q = 0; q < 2; q++) {
                const int off = (r0 + 4*q) ^ swcv;
                float4 v0 = *reinterpret_cast<const float4 *>(b0p + off);
                float4 v1 = *reinterpret_cast<const float4 *>(b1p + off);
                float a0, a1, a2, a3;
                upk2(acc[2*q][c],   a0, a1);
                upk2(acc[2*q+1][c], a2, a3);
                float4 v;
                v.x = a0 + v0.x + v1.x;
                v.y = a1 + v0.y + v1.y;
                v.z = a2 + v0.z + v1.z;
                v.w = a3 + v0.w + v1.w;
                *reinterpret_cast<float4 *>(b0p + off) = v;
            }
        }
    }
    __syncthreads();

    // ---- ks0: acc + red0 (bias already in acc), tanh -> Aout ----
    if (ks == 0) {
#pragma unroll
        for (int c = 0; c < CPL; c++) {
            const int cc  = c0 + c;
            const int swcv = SWR(cc);
            const float *b0p = red0 + cc * TM;
            float *dst = Aout + cc * TM;
#pragma unroll
            for (int q = 0; q < 2; q++) {
                const int off = (r0 + 4*q) ^ swcv;
                float4 v0 = *reinterpret_cast<const float4 *>(b0p + off);
                float a0, a1, a2, a3;
                upk2(acc[2*q][c],   a0, a1);
                upk2(acc[2*q+1][c], a2, a3);
                float4 v;
                v.x = a0 + v0.x;
                v.y = a1 + v0.y;
                v.z = a2 + v0.z;
                v.w = a3 + v0.w;
                if (ACT) {
                    v.x = tanhf(v.x); v.y = tanhf(v.y);
                    v.z = tanhf(v.z); v.w = tanhf(v.w);
                }
                *reinterpret_cast<float4 *>(dst + off) = v;
            }
        }
    }
    __syncthreads();
}

// ---------------------------------------------------------------------------
__global__ void __launch_bounds__(THREADS, 2)
node_kernel(const float *__restrict__ ts, const float *__restrict__ y0,
            const float *__restrict__ W0, const float *__restrict__ b0,
            const float *__restrict__ W1, const float *__restrict__ b1,
            const float *__restrict__ W2, const float *__restrict__ b2,
            const float *__restrict__ W3, const float *__restrict__ b3,
            float *__restrict__ out) {
    extern __shared__ float sm[];
    float *actA = sm;                       // [256][16] row-swizzled
    float *actB = actA + ACT_SIZE;
    float *red0 = actB + ACT_SIZE;
    float *red1 = red0 + RED_SIZE;
    float *zbuf = red1 + RED_SIZE;          // [64][16] row-swizzled
    float *ybuf = zbuf + ZK_SIZE;
    float *kbuf = ybuf + ZK_SIZE;           // 6 * [64][16]

    const int tid = threadIdx.x;
    const int cta = blockIdx.x;

    // ingest y0 (row-major) -> ybuf (transposed, row-swizzled); emit out[0]
    {
        const float *y0c = y0 + (size_t)cta * TM * DIM;
        float *o0 = out + (size_t)cta * TM * DIM;
        for (int i = tid; i < TM * DIM; i += THREADS) {
            const int r = i >> 6;       // 0..15
            const int d = i & 63;
            float v = __ldg(y0c + i);
            ybuf[d * TM + (r ^ SWR(d))] = v;
            o0[i] = v;
        }
    }
    __syncthreads();

    for (int t = 1; t < NTT; ++t) {
        const float h = __ldg(ts + t) - __ldg(ts + t - 1);

        for (int s = 0; s < 6; ++s) {
            const float *zin;
            if (s == 0) {
                zin = ybuf;
            } else {
                // z = y + h * sum_{j<s} A[s][j]*k_j (elementwise, same layout)
                float4 *zb = reinterpret_cast<float4 *>(zbuf);
                const float4 *yb = reinterpret_cast<const float4 *>(ybuf);
                for (int i = tid; i < ZK_SIZE / 4; i += THREADS) {
                    float4 v = yb[i];
                    for (int j = 0; j < s; j++) {
                        float c = h * c_A[s][j];
                        float4 kv = reinterpret_cast<const float4 *>(kbuf + j * ZK_SIZE)[i];
                        v.x += c * kv.x; v.y += c * kv.y;
                        v.z += c * kv.z; v.w += c * kv.w;
                    }
                    zb[i] = v;
                }
                __syncthreads();
                zin = zbuf;
            }

            layerT<DIM,   WIDTH, true >(zin,  actA, W0, b0, red0, red1);
            layerT<WIDTH, WIDTH, true >(actA, actB, W1, b1, red0, red1);
            layerT<WIDTH, WIDTH, true >(actB, actA, W2, b2, red0, red1);
            layerT<WIDTH, DIM,   false>(actA, kbuf + s * ZK_SIZE, W3, b3, red0, red1);
        }

        // y += h * sum_j B[j]*k_j (elementwise)
        {
            float4 *yb = reinterpret_cast<float4 *>(ybuf);
            for (int i = tid; i < ZK_SIZE / 4; i += THREADS) {
                float4 v = yb[i];
#pragma unroll
                for (int j = 0; j < 6; j++) {
                    float c = h * c_B[j];
                    float4 kv = reinterpret_cast<const float4 *>(kbuf + j * ZK_SIZE)[i];
                    v.x += c * kv.x; v.y += c * kv.y;
                    v.z += c * kv.z; v.w += c * kv.w;
                }
                yb[i] = v;
            }
        }
        __syncthreads();

        // store out[t] (row-major, coalesced) from swizzled ybuf
        {
            float *outc = out + (size_t)t * (BATCH * DIM) + (size_t)cta * TM * DIM;
            for (int i = tid; i < TM * DIM; i += THREADS) {
                const int r = i >> 6;
                const int d = i & 63;
                outc[i] = ybuf[d * TM + (r ^ SWR(d))];
            }
        }
        __syncthreads();
    }
}

// ---------------------------------------------------------------------------
extern "C" void kernel_launch(void *const *d_in, const int *in_sizes, int n_in,
                              void *d_out, int out_size) {
    const float *ts = (const float *)d_in[0];
    const float *y0 = (const float *)d_in[1];
    const float *W0 = (const float *)d_in[2];
    const float *b0 = (const float *)d_in[3];
    const float *W1 = (const float *)d_in[4];
    const float *b1 = (const float *)d_in[5];
    const float *W2 = (const float *)d_in[6];
    const float *b2 = (const float *)d_in[7];
    const float *W3 = (const float *)d_in[8];
    const float *b3 = (const float *)d_in[9];
    float *out = (float *)d_out;

    cudaFuncSetAttribute(node_kernel,
                         cudaFuncAttributeMaxDynamicSharedMemorySize, SMEM_BYTES);
    node_kernel<<<NCTA, THREADS, SMEM_BYTES>>>(ts, y0, W0, b0, W1, b1,
                                               W2, b2, W3, b3, out);
}